// round 13
// baseline (speedup 1.0000x reference)
#include <cuda_runtime.h>
#include <cuda_fp16.h>
#include <cstdint>
#include <math.h>

// N=4, S=4096, E=1024, H=16, D=64
// fused convert(x,W,bias) -> fp16 | ONE merged QKV GEMM [16384,3072] fp16-out
// | smem-free head-gram attention (fp16 in/out, scrambled store) | final GEMM
// fp32-out. Legacy HMMA path (tcgen05 rejected at compute_103 target).
// R13: CTA tile 256x128, warp tile 64x64 (4Mx2N) -> 33% less smem read
// traffic per FLOP; smem crossbar no longer co-critical with tensor pipe.

// ---------------- scratch (alloc-guard compliant device globals) ----------
__device__ __half g_Xh[16777216];      // x in fp16
__device__ __half g_QKVh[50331648];    // QKV merged output [16384,3072] fp16
__device__ __half g_Oh[16777216];      // attn out, scrambled, fp16
__device__ __half g_Wh[4194304];       // Wq,Wk,Wv,Wo in fp16 (concat)
__device__ float  g_bias[3072];        // bq|bk|bv concat

__device__ __forceinline__ uint32_t smem_u32(const void* p) {
    uint32_t a;
    asm("{ .reg .u64 t; cvta.to.shared.u64 t, %1; cvt.u32.u64 %0, t; }"
        : "=r"(a) : "l"(p));
    return a;
}

// ---------------------------------------------------------------------------
// fp16 GEMM: C[16384,NC] = Ah[16384,1024] @ Bh[NC,1024]^T + bias (fp32 acc)
// CTA tile 256x128, BK=32, 4-stage cp.async pipeline, 8 warps (4Mx2N),
// warp tile 64x64, mma.sync.m16n8k16 (4x8 atoms x 2 k-steps per K-tile).
// smem row pitch 80B: 16B-aligned cp.async dsts AND conflict-free ldmatrix
// (banks (20r+c) mod 32 cover all 32 for rows r=0..7 of each phase).
// ---------------------------------------------------------------------------
static constexpr int GH_A_B     = 20480;           // 256 rows * 80B
static constexpr int GH_STAGE_B = 30720;           // (256 A + 128 B) * 80B
static constexpr int GH_SMEM    = 4 * GH_STAGE_B;  // 122880

template <typename OutT>
__global__ __launch_bounds__(256, 1)
void gemm_h(const __half* __restrict__ A, const __half* __restrict__ B,
            const float* __restrict__ bias, OutT* __restrict__ C, int ldc) {
    extern __shared__ __align__(128) char smem[];
    const uint32_t sb = smem_u32(smem);
    const int tid = threadIdx.x;
    const int warp = tid >> 5, lane = tid & 31;
    const int wm = (warp & 3) * 64;     // 4 warps along M
    const int wn = (warp >> 2) * 64;    // 2 warps along N

    const __half* Ab = A + (size_t)blockIdx.y * 256 * 1024;
    const __half* Bb = B + (size_t)blockIdx.x * 128 * 1024;

    float acc[4][8][4];
#pragma unroll
    for (int i = 0; i < 4; i++)
#pragma unroll
        for (int j = 0; j < 8; j++)
#pragma unroll
            for (int k = 0; k < 4; k++) acc[i][j][k] = 0.f;

    auto load_stage = [&](int v) {
        const uint32_t base = sb + (uint32_t)(v & 3) * GH_STAGE_B;
        const int kb = v * 32;
        // A: 256 rows x 32 halfs (4 x 16B chunks per row)
#pragma unroll
        for (int i = 0; i < 4; i++) {
            const int c = tid + i * 256;       // 0..1023
            const int row = c >> 2, ch = c & 3;
            const uint32_t da = base + (uint32_t)(row * 80 + ch * 16);
            asm volatile("cp.async.cg.shared.global [%0], [%1], 16;"
                         :: "r"(da), "l"(Ab + (size_t)row * 1024 + kb + ch * 8));
        }
        // B: 128 rows x 32 halfs
#pragma unroll
        for (int i = 0; i < 2; i++) {
            const int c = tid + i * 256;       // 0..511
            const int row = c >> 2, ch = c & 3;
            const uint32_t db = base + GH_A_B + (uint32_t)(row * 80 + ch * 16);
            asm volatile("cp.async.cg.shared.global [%0], [%1], 16;"
                         :: "r"(db), "l"(Bb + (size_t)row * 1024 + kb + ch * 8));
        }
    };

    load_stage(0); asm volatile("cp.async.commit_group;");
    load_stage(1); asm volatile("cp.async.commit_group;");
    load_stage(2); asm volatile("cp.async.commit_group;");

    // ldmatrix per-lane address components
    const int arow80 = (lane & 15) * 80;            // A rows m0..m0+15
    const int asel   = (lane >> 4) * 16;            // A: k or k+8 (bytes)
    const int brow80 = ((lane & 7) + ((lane >> 4) & 1) * 8) * 80;  // B rows n
    const int bsel   = ((lane >> 3) & 1) * 16;      // B: k or k+8 (bytes)

    for (int kt = 0; kt < 32; kt++) {
        asm volatile("cp.async.wait_group 2;");
        __syncthreads();                  // stage kt resident for all threads
        if (kt + 3 < 32) load_stage(kt + 3);
        asm volatile("cp.async.commit_group;");

        const uint32_t Abase = sb + (uint32_t)(kt & 3) * GH_STAGE_B;
        const uint32_t Bbase = Abase + GH_A_B;
#pragma unroll
        for (int ks = 0; ks < 2; ks++) {
            const int k0b = ks * 32;      // 16 halfs = 32 bytes
            uint32_t a[4][4];
#pragma unroll
            for (int am = 0; am < 4; am++) {
                const uint32_t ad = Abase +
                    (uint32_t)((wm + am * 16) * 80 + arow80 + k0b + asel);
                asm volatile(
                    "ldmatrix.sync.aligned.m8n8.x4.shared.b16 {%0,%1,%2,%3}, [%4];"
                    : "=r"(a[am][0]), "=r"(a[am][1]), "=r"(a[am][2]), "=r"(a[am][3])
                    : "r"(ad));
            }
            uint32_t b[8][2];
#pragma unroll
            for (int g = 0; g < 4; g++) {
                const uint32_t bd = Bbase +
                    (uint32_t)((wn + g * 16) * 80 + brow80 + k0b + bsel);
                uint32_t r0, r1, r2, r3;
                asm volatile(
                    "ldmatrix.sync.aligned.m8n8.x4.shared.b16 {%0,%1,%2,%3}, [%4];"
                    : "=r"(r0), "=r"(r1), "=r"(r2), "=r"(r3) : "r"(bd));
                b[2 * g][0] = r0; b[2 * g][1] = r1;
                b[2 * g + 1][0] = r2; b[2 * g + 1][1] = r3;
            }
#pragma unroll
            for (int am = 0; am < 4; am++)
#pragma unroll
                for (int bn = 0; bn < 8; bn++)
                    asm volatile(
                        "mma.sync.aligned.m16n8k16.row.col.f32.f16.f16.f32 "
                        "{%0,%1,%2,%3}, {%4,%5,%6,%7}, {%8,%9}, {%0,%1,%2,%3};"
                        : "+f"(acc[am][bn][0]), "+f"(acc[am][bn][1]),
                          "+f"(acc[am][bn][2]), "+f"(acc[am][bn][3])
                        : "r"(a[am][0]), "r"(a[am][1]), "r"(a[am][2]), "r"(a[am][3]),
                          "r"(b[bn][0]), "r"(b[bn][1]));
        }
    }

    // epilogue: bias add + stores (fp32 or fp16 out)
    const int rowBase = blockIdx.y * 256 + wm + (lane >> 2);
    const int colBase = blockIdx.x * 128 + wn;
#pragma unroll
    for (int bn = 0; bn < 8; bn++) {
        const int col = colBase + bn * 8 + (lane & 3) * 2;
        const float b0 = bias[col];
        const float b1 = bias[col + 1];
#pragma unroll
        for (int am = 0; am < 4; am++) {
            const int row = rowBase + am * 16;
            if constexpr (sizeof(OutT) == 4) {
                float2 v;
                v.x = acc[am][bn][0] + b0;
                v.y = acc[am][bn][1] + b1;
                *(float2*)&C[(size_t)row * ldc + col] = v;
                v.x = acc[am][bn][2] + b0;
                v.y = acc[am][bn][3] + b1;
                *(float2*)&C[(size_t)(row + 8) * ldc + col] = v;
            } else {
                __half2 h;
                h = __floats2half2_rn(acc[am][bn][0] + b0, acc[am][bn][1] + b1);
                *(__half2*)&C[(size_t)row * ldc + col] = h;
                h = __floats2half2_rn(acc[am][bn][2] + b0, acc[am][bn][3] + b1);
                *(__half2*)&C[(size_t)(row + 8) * ldc + col] = h;
            }
        }
    }
}

// ---------------------------------------------------------------------------
// smem-free head-gram attention, fp16 in (QKV merged rows of 3072) / fp16 out.
// 2 positions per 256-thread block; thread (q in 0..15, j in 0..7) owns
// d-slice [8j,8j+8). Gram reduced via 3 shfl.bfly steps in 8-lane group;
// softmax redundant per group (no barriers). Store folds scrambled reshape
// row' = q*256 + s/16, col' = (s%16)*64 + d.
// ---------------------------------------------------------------------------
__device__ __forceinline__ void h8_to_f(const __half* p, float* f) {
    const uint4 u = *(const uint4*)p;
    float2 t;
    t = __half22float2(*(const __half2*)&u.x); f[0] = t.x; f[1] = t.y;
    t = __half22float2(*(const __half2*)&u.y); f[2] = t.x; f[3] = t.y;
    t = __half22float2(*(const __half2*)&u.z); f[4] = t.x; f[5] = t.y;
    t = __half22float2(*(const __half2*)&u.w); f[6] = t.x; f[7] = t.y;
}

__global__ __launch_bounds__(256)
void attn_kernel() {
    const int pos = blockIdx.x * 2 + (threadIdx.x >> 7);
    const int t = threadIdx.x & 127;
    const int s = pos & 4095;
    const int n = pos >> 12;
    const int q = t >> 3;
    const int d0 = (t & 7) * 8;

    const __half* base = g_QKVh + (size_t)pos * 3072;
    const __half* Qp = base + q * 64 + d0;
    const __half* Kp = base + 1024 + d0;
    const __half* Vp = base + 2048 + d0;

    float qf[8];
    h8_to_f(Qp, qf);

    float sc[16];
#pragma unroll
    for (int l = 0; l < 16; l++) {
        float kf[8];
        h8_to_f(Kp + l * 64, kf);
        float a = qf[0] * kf[0];
#pragma unroll
        for (int j = 1; j < 8; j++) a = fmaf(qf[j], kf[j], a);
        sc[l] = a;
    }
#pragma unroll
    for (int l = 0; l < 16; l++) {
        sc[l] += __shfl_xor_sync(0xffffffffu, sc[l], 1);
        sc[l] += __shfl_xor_sync(0xffffffffu, sc[l], 2);
        sc[l] += __shfl_xor_sync(0xffffffffu, sc[l], 4);
        sc[l] *= 0.125f;  // 1/sqrt(64)
    }
    float mx = sc[0];
#pragma unroll
    for (int l = 1; l < 16; l++) mx = fmaxf(mx, sc[l]);
    float sum = 0.f;
#pragma unroll
    for (int l = 0; l < 16; l++) { sc[l] = __expf(sc[l] - mx); sum += sc[l]; }
    const float inv = 1.0f / sum;

    float o[8];
#pragma unroll
    for (int j = 0; j < 8; j++) o[j] = 0.f;
#pragma unroll
    for (int l = 0; l < 16; l++) {
        const float w = sc[l] * inv;
        float vf[8];
        h8_to_f(Vp + l * 64, vf);
#pragma unroll
        for (int j = 0; j < 8; j++) o[j] = fmaf(w, vf[j], o[j]);
    }

    __half2 h0 = __floats2half2_rn(o[0], o[1]);
    __half2 h1 = __floats2half2_rn(o[2], o[3]);
    __half2 h2 = __floats2half2_rn(o[4], o[5]);
    __half2 h3 = __floats2half2_rn(o[6], o[7]);
    uint4 out;
    out.x = *(uint32_t*)&h0;
    out.y = *(uint32_t*)&h1;
    out.z = *(uint32_t*)&h2;
    out.w = *(uint32_t*)&h3;

    __half* op = g_Oh + (((size_t)n << 12) + (q << 8) + (s >> 4)) * 1024
               + (s & 15) * 64 + d0;
    *(uint4*)op = out;
}

// ---------------- fused conversion: x + 4 weights + bias concat ------------
__global__ __launch_bounds__(256)
void conv_fused(const float4* __restrict__ x,
                const float4* __restrict__ wq, const float4* __restrict__ wk,
                const float4* __restrict__ wv, const float4* __restrict__ wo,
                const float4* __restrict__ bq, const float4* __restrict__ bk,
                const float4* __restrict__ bv) {
    const int i = blockIdx.x * 256 + threadIdx.x;
    float4 v;
    uint2* dst;
    if (i < 4194304) {
        v = x[i];
        dst = (uint2*)g_Xh + i;
    } else {
        const int w = i - 4194304;           // 0..1048575
        const int seg = w >> 18;             // 0..3
        const int off = w & 262143;
        v = (seg == 0) ? wq[off] : (seg == 1) ? wk[off]
          : (seg == 2) ? wv[off] : wo[off];
        dst = (uint2*)g_Wh + w;
    }
    __half2 h0 = __floats2half2_rn(v.x, v.y);
    __half2 h1 = __floats2half2_rn(v.z, v.w);
    uint2 o;
    o.x = *(uint32_t*)&h0;
    o.y = *(uint32_t*)&h1;
    *dst = o;

    if (i < 768) {  // bias concat (3072 floats = 768 float4)
        float4 b = (i < 256) ? bq[i] : (i < 512) ? bk[i - 256] : bv[i - 512];
        ((float4*)g_bias)[i] = b;
    }
}

// ---------------- launch ---------------------------------------------------
extern "C" void kernel_launch(void* const* d_in, const int* in_sizes, int n_in,
                              void* d_out, int out_size) {
    const float* x  = (const float*)d_in[0];
    const float* Wq = (const float*)d_in[1];
    const float* bq = (const float*)d_in[2];
    const float* Wk = (const float*)d_in[3];
    const float* bk = (const float*)d_in[4];
    const float* Wv = (const float*)d_in[5];
    const float* bv = (const float*)d_in[6];
    const float* Wo = (const float*)d_in[7];
    const float* bo = (const float*)d_in[8];

    __half *pXh, *pWh, *pOh, *pQKV;
    float *pBias;
    cudaGetSymbolAddress((void**)&pXh,  g_Xh);
    cudaGetSymbolAddress((void**)&pWh,  g_Wh);
    cudaGetSymbolAddress((void**)&pOh,  g_Oh);
    cudaGetSymbolAddress((void**)&pQKV, g_QKVh);
    cudaGetSymbolAddress((void**)&pBias, g_bias);

    cudaFuncSetAttribute(gemm_h<__half>,
                         cudaFuncAttributeMaxDynamicSharedMemorySize, GH_SMEM);
    cudaFuncSetAttribute(gemm_h<float>,
                         cudaFuncAttributeMaxDynamicSharedMemorySize, GH_SMEM);

    conv_fused<<<20480, 256>>>((const float4*)x,
                               (const float4*)Wq, (const float4*)Wk,
                               (const float4*)Wv, (const float4*)Wo,
                               (const float4*)bq, (const float4*)bk,
                               (const float4*)bv);

    // merged QKV GEMM: C[16384,3072] fp16
    gemm_h<__half><<<dim3(24, 64), 256, GH_SMEM>>>(pXh, pWh, pBias, pQKV, 3072);
    attn_kernel<<<8192, 256>>>();
    // final GEMM: fp32 out
    gemm_h<float><<<dim3(8, 64), 256, GH_SMEM>>>(pOh, pWh + 3145728, bo,
                                                 (float*)d_out, 1024);
}

// round 14
// speedup vs baseline: 1.2919x; 1.2919x over previous
#include <cuda_runtime.h>
#include <cuda_fp16.h>
#include <cstdint>
#include <math.h>

// N=4, S=4096, E=1024, H=16, D=64
// fused convert(x,W,bias) -> fp16 | ONE merged QKV GEMM [16384,3072] fp16-out
// | tensor-core head-gram attention (warp/position, fp16 in/out, scrambled
// store) | final GEMM fp32-out. Legacy HMMA path (tcgen05 rejected at
// compute_103 target). GEMMs identical to the 535us R12 config (measured
// ~95% of the fp32-acc HMMA pipe, rt=16/SMSP).

// ---------------- scratch (alloc-guard compliant device globals) ----------
__device__ __half g_Xh[16777216];      // x in fp16
__device__ __half g_QKVh[50331648];    // QKV merged output [16384,3072] fp16
__device__ __half g_Oh[16777216];      // attn out, scrambled, fp16
__device__ __half g_Wh[4194304];       // Wq,Wk,Wv,Wo in fp16 (concat)
__device__ float  g_bias[3072];        // bq|bk|bv concat

__device__ __forceinline__ uint32_t smem_u32(const void* p) {
    uint32_t a;
    asm("{ .reg .u64 t; cvta.to.shared.u64 t, %1; cvt.u32.u64 %0, t; }"
        : "=r"(a) : "l"(p));
    return a;
}

#define LDMX4(r0, r1, r2, r3, addr) \
    asm volatile("ldmatrix.sync.aligned.m8n8.x4.shared.b16 {%0,%1,%2,%3}, [%4];" \
                 : "=r"(r0), "=r"(r1), "=r"(r2), "=r"(r3) : "r"(addr))
#define LDMX4T(r0, r1, r2, r3, addr) \
    asm volatile("ldmatrix.sync.aligned.m8n8.x4.trans.shared.b16 {%0,%1,%2,%3}, [%4];" \
                 : "=r"(r0), "=r"(r1), "=r"(r2), "=r"(r3) : "r"(addr))
#define MMA16816(acc, a0, a1, a2, a3, b0, b1) \
    asm volatile("mma.sync.aligned.m16n8k16.row.col.f32.f16.f16.f32 " \
                 "{%0,%1,%2,%3}, {%4,%5,%6,%7}, {%8,%9}, {%0,%1,%2,%3};" \
                 : "+f"((acc)[0]), "+f"((acc)[1]), "+f"((acc)[2]), "+f"((acc)[3]) \
                 : "r"(a0), "r"(a1), "r"(a2), "r"(a3), "r"(b0), "r"(b1))

// ---------------------------------------------------------------------------
// fp16 GEMM: C[16384,NC] = Ah[16384,1024] @ Bh[NC,1024]^T + bias (fp32 acc)
// CTA tile 128x128, BK=32, 4-stage cp.async pipeline, 8 warps (2Mx4N),
// warp tile 64x32, mma.sync.m16n8k16. smem pitch 80B (conflict-free ldmatrix).
// ---------------------------------------------------------------------------
static constexpr int GH_STAGE_B = 20480;           // (128+128) rows * 80B
static constexpr int GH_SMEM    = 4 * GH_STAGE_B;  // 81920

template <typename OutT>
__global__ __launch_bounds__(256, 2)
void gemm_h(const __half* __restrict__ A, const __half* __restrict__ B,
            const float* __restrict__ bias, OutT* __restrict__ C, int ldc) {
    extern __shared__ __align__(128) char smem[];
    const uint32_t sb = smem_u32(smem);
    const int tid = threadIdx.x;
    const int warp = tid >> 5, lane = tid & 31;
    const int wm = (warp & 1) * 64;
    const int wn = (warp >> 1) * 32;

    const __half* Ab = A + (size_t)blockIdx.y * 128 * 1024;
    const __half* Bb = B + (size_t)blockIdx.x * 128 * 1024;

    float acc[4][4][4];
#pragma unroll
    for (int i = 0; i < 4; i++)
#pragma unroll
        for (int j = 0; j < 4; j++)
#pragma unroll
            for (int k = 0; k < 4; k++) acc[i][j][k] = 0.f;

    auto load_stage = [&](int v) {
        const uint32_t base = sb + (uint32_t)(v & 3) * GH_STAGE_B;
        const int kb = v * 32;
#pragma unroll
        for (int i = 0; i < 2; i++) {
            const int c = tid + i * 256;     // 0..511
            const int row = c >> 2, ch = c & 3;
            const uint32_t da = base + (uint32_t)(row * 80 + ch * 16);
            asm volatile("cp.async.cg.shared.global [%0], [%1], 16;"
                         :: "r"(da), "l"(Ab + (size_t)row * 1024 + kb + ch * 8));
            const uint32_t db = base + 10240u + (uint32_t)(row * 80 + ch * 16);
            asm volatile("cp.async.cg.shared.global [%0], [%1], 16;"
                         :: "r"(db), "l"(Bb + (size_t)row * 1024 + kb + ch * 8));
        }
    };

    load_stage(0); asm volatile("cp.async.commit_group;");
    load_stage(1); asm volatile("cp.async.commit_group;");
    load_stage(2); asm volatile("cp.async.commit_group;");

    const int arow80 = (lane & 15) * 80;
    const int asel   = (lane >> 4) * 16;
    const int brow80 = ((lane & 7) + ((lane >> 4) & 1) * 8) * 80;
    const int bsel   = ((lane >> 3) & 1) * 16;

    for (int kt = 0; kt < 32; kt++) {
        asm volatile("cp.async.wait_group 2;");
        __syncthreads();
        if (kt + 3 < 32) load_stage(kt + 3);
        asm volatile("cp.async.commit_group;");

        const uint32_t Abase = sb + (uint32_t)(kt & 3) * GH_STAGE_B;
        const uint32_t Bbase = Abase + 10240u;
#pragma unroll
        for (int ks = 0; ks < 2; ks++) {
            const int k0b = ks * 32;
            uint32_t a[4][4];
#pragma unroll
            for (int am = 0; am < 4; am++) {
                const uint32_t ad = Abase +
                    (uint32_t)((wm + am * 16) * 80 + arow80 + k0b + asel);
                LDMX4(a[am][0], a[am][1], a[am][2], a[am][3], ad);
            }
            uint32_t b[4][2];
#pragma unroll
            for (int g = 0; g < 2; g++) {
                const uint32_t bd = Bbase +
                    (uint32_t)((wn + g * 16) * 80 + brow80 + k0b + bsel);
                uint32_t r0, r1, r2, r3;
                LDMX4(r0, r1, r2, r3, bd);
                b[2 * g][0] = r0; b[2 * g][1] = r1;
                b[2 * g + 1][0] = r2; b[2 * g + 1][1] = r3;
            }
#pragma unroll
            for (int am = 0; am < 4; am++)
#pragma unroll
                for (int bn = 0; bn < 4; bn++)
                    MMA16816(acc[am][bn], a[am][0], a[am][1], a[am][2], a[am][3],
                             b[bn][0], b[bn][1]);
        }
    }

    const int rowBase = blockIdx.y * 128 + wm + (lane >> 2);
    const int colBase = blockIdx.x * 128 + wn;
#pragma unroll
    for (int bn = 0; bn < 4; bn++) {
        const int col = colBase + bn * 8 + (lane & 3) * 2;
        const float b0 = bias[col];
        const float b1 = bias[col + 1];
#pragma unroll
        for (int am = 0; am < 4; am++) {
            const int row = rowBase + am * 16;
            if constexpr (sizeof(OutT) == 4) {
                float2 v;
                v.x = acc[am][bn][0] + b0;
                v.y = acc[am][bn][1] + b1;
                *(float2*)&C[(size_t)row * ldc + col] = v;
                v.x = acc[am][bn][2] + b0;
                v.y = acc[am][bn][3] + b1;
                *(float2*)&C[(size_t)(row + 8) * ldc + col] = v;
            } else {
                __half2 h;
                h = __floats2half2_rn(acc[am][bn][0] + b0, acc[am][bn][1] + b1);
                *(__half2*)&C[(size_t)row * ldc + col] = h;
                h = __floats2half2_rn(acc[am][bn][2] + b0, acc[am][bn][3] + b1);
                *(__half2*)&C[(size_t)(row + 8) * ldc + col] = h;
            }
        }
    }
}

// ---------------------------------------------------------------------------
// Tensor-core head-gram attention: ONE WARP PER POSITION.
// Per position (n,s): G = Q(16x64) K^T -> softmax rows -> out = P V(16x64).
// QKV staged to warp-private smem (48 rows x 64 halfs, pitch 144B: bank
// starts 4r mod 32 distinct => conflict-free ldmatrix). Gram: 4 k-steps of
// (A=Q ldmatrix.x4, B=K ldmatrix.x4 [K rows are n-major => B frag directly],
// 2 MMA). Softmax on C frags via quad shuffles. P fp16 A-frags packed
// straight from C regs (C(m16n8) pair layout == A(m16k16) half2 layout).
// Out: V via ldmatrix.x4.trans (V rows are k-major), 8 MMA. Store folds
// the reference's scrambled flat reshape: row' = q*256 + s/16,
// col' = (s%16)*64 + d. No __syncthreads anywhere (warp-private staging).
// ---------------------------------------------------------------------------
static constexpr int ATT_WB   = 48 * 144;           // 6912 B per warp
static constexpr int ATT_SMEM = 8 * ATT_WB;         // 55296 B per block

__global__ __launch_bounds__(256)
void attn_mma() {
    extern __shared__ __align__(128) char asmem[];
    const int warpId = threadIdx.x >> 5;
    const int lane = threadIdx.x & 31;
    const int pos = blockIdx.x * 8 + warpId;
    const int s = pos & 4095;
    const int n = pos >> 12;

    const uint32_t wb = smem_u32(asmem) + (uint32_t)warpId * ATT_WB;
    const __half* src = g_QKVh + (size_t)pos * 3072;

    // stage 48 rows (Q:0-15, K:16-31, V:32-47), 64 halfs each, pitch 144B
#pragma unroll
    for (int it = 0; it < 12; it++) {
        const int id = it * 32 + lane;          // 0..383
        const int rr = id >> 3, cc = id & 7;
        const uint32_t dst = wb + (uint32_t)(rr * 144 + cc * 16);
        asm volatile("cp.async.cg.shared.global [%0], [%1], 16;"
                     :: "r"(dst), "l"(src + rr * 64 + cc * 8));
    }
    asm volatile("cp.async.commit_group;");
    asm volatile("cp.async.wait_group 0;");
    __syncwarp();

    const uint32_t Qb = wb;
    const uint32_t Kb = wb + 16 * 144;
    const uint32_t Vb = wb + 32 * 144;

    // ---- gram: C[2][4] covers 16x16 scores (2 n-octs) ----
    float c0[4] = {0.f, 0.f, 0.f, 0.f};
    float c1[4] = {0.f, 0.f, 0.f, 0.f};
    const uint32_t aAddr = Qb + (uint32_t)((lane & 15) * 144 + (lane >> 4) * 16);
    const uint32_t bAddr = Kb + (uint32_t)(((lane & 7) + ((lane >> 4) << 3)) * 144
                                           + ((lane >> 3) & 1) * 16);
#pragma unroll
    for (int kk = 0; kk < 4; kk++) {
        uint32_t a0, a1, a2, a3, m0, m1, m2, m3;
        LDMX4(a0, a1, a2, a3, aAddr + kk * 32);
        LDMX4(m0, m1, m2, m3, bAddr + kk * 32);
        MMA16816(c0, a0, a1, a2, a3, m0, m1);
        MMA16816(c1, a0, a1, a2, a3, m2, m3);
    }

    // ---- softmax on fragments (rows r = lane>>2 and r+8) ----
    float r0v[4] = {c0[0] * 0.125f, c0[1] * 0.125f, c1[0] * 0.125f, c1[1] * 0.125f};
    float r1v[4] = {c0[2] * 0.125f, c0[3] * 0.125f, c1[2] * 0.125f, c1[3] * 0.125f};
    float mx0 = fmaxf(fmaxf(r0v[0], r0v[1]), fmaxf(r0v[2], r0v[3]));
    float mx1 = fmaxf(fmaxf(r1v[0], r1v[1]), fmaxf(r1v[2], r1v[3]));
    mx0 = fmaxf(mx0, __shfl_xor_sync(0xffffffffu, mx0, 1));
    mx0 = fmaxf(mx0, __shfl_xor_sync(0xffffffffu, mx0, 2));
    mx1 = fmaxf(mx1, __shfl_xor_sync(0xffffffffu, mx1, 1));
    mx1 = fmaxf(mx1, __shfl_xor_sync(0xffffffffu, mx1, 2));
    float s0 = 0.f, s1 = 0.f;
#pragma unroll
    for (int i = 0; i < 4; i++) {
        r0v[i] = __expf(r0v[i] - mx0); s0 += r0v[i];
        r1v[i] = __expf(r1v[i] - mx1); s1 += r1v[i];
    }
    s0 += __shfl_xor_sync(0xffffffffu, s0, 1);
    s0 += __shfl_xor_sync(0xffffffffu, s0, 2);
    s1 += __shfl_xor_sync(0xffffffffu, s1, 1);
    s1 += __shfl_xor_sync(0xffffffffu, s1, 2);
    const float inv0 = 1.0f / s0, inv1 = 1.0f / s1;

    // ---- pack P to fp16 A-frags (direct C->A layout identity) ----
    __half2 pa0 = __floats2half2_rn(r0v[0] * inv0, r0v[1] * inv0);  // (r,   k 2c)
    __half2 pa1 = __floats2half2_rn(r1v[0] * inv1, r1v[1] * inv1);  // (r+8, k 2c)
    __half2 pa2 = __floats2half2_rn(r0v[2] * inv0, r0v[3] * inv0);  // (r,   k 2c+8)
    __half2 pa3 = __floats2half2_rn(r1v[2] * inv1, r1v[3] * inv1);  // (r+8, k 2c+8)
    const uint32_t p0 = *(uint32_t*)&pa0, p1 = *(uint32_t*)&pa1;
    const uint32_t p2 = *(uint32_t*)&pa2, p3 = *(uint32_t*)&pa3;

    // ---- out = P @ V : 8 n-chunks of 8 cols ----
    float o[8][4];
#pragma unroll
    for (int ch = 0; ch < 8; ch++)
#pragma unroll
        for (int k = 0; k < 4; k++) o[ch][k] = 0.f;
    const uint32_t vAddr = Vb + (uint32_t)((lane & 15) * 144 + (lane >> 4) * 16);
#pragma unroll
    for (int i = 0; i < 4; i++) {
        uint32_t m0, m1, m2, m3;
        LDMX4T(m0, m1, m2, m3, vAddr + i * 32);
        MMA16816(o[2 * i],     p0, p1, p2, p3, m0, m1);
        MMA16816(o[2 * i + 1], p0, p1, p2, p3, m2, m3);
    }

    // ---- scrambled store, fp16 ----
    const int r = lane >> 2, c2 = (lane & 3) * 2;
    const size_t base2 = (((size_t)n << 12) + (size_t)(s >> 4)) * 1024
                       + (size_t)(s & 15) * 64;
#pragma unroll
    for (int ch = 0; ch < 8; ch++) {
        const int d = ch * 8 + c2;
        __half2 lo = __floats2half2_rn(o[ch][0], o[ch][1]);
        __half2 hi = __floats2half2_rn(o[ch][2], o[ch][3]);
        *(__half2*)&g_Oh[base2 + (size_t)r * 262144 + d] = lo;
        *(__half2*)&g_Oh[base2 + (size_t)(r + 8) * 262144 + d] = hi;
    }
}

// ---------------- fused conversion: x + 4 weights + bias concat ------------
__global__ __launch_bounds__(256)
void conv_fused(const float4* __restrict__ x,
                const float4* __restrict__ wq, const float4* __restrict__ wk,
                const float4* __restrict__ wv, const float4* __restrict__ wo,
                const float4* __restrict__ bq, const float4* __restrict__ bk,
                const float4* __restrict__ bv) {
    const int i = blockIdx.x * 256 + threadIdx.x;
    float4 v;
    uint2* dst;
    if (i < 4194304) {
        v = x[i];
        dst = (uint2*)g_Xh + i;
    } else {
        const int w = i - 4194304;           // 0..1048575
        const int seg = w >> 18;             // 0..3
        const int off = w & 262143;
        v = (seg == 0) ? wq[off] : (seg == 1) ? wk[off]
          : (seg == 2) ? wv[off] : wo[off];
        dst = (uint2*)g_Wh + w;
    }
    __half2 h0 = __floats2half2_rn(v.x, v.y);
    __half2 h1 = __floats2half2_rn(v.z, v.w);
    uint2 o;
    o.x = *(uint32_t*)&h0;
    o.y = *(uint32_t*)&h1;
    *dst = o;

    if (i < 768) {  // bias concat (3072 floats = 768 float4)
        float4 b = (i < 256) ? bq[i] : (i < 512) ? bk[i - 256] : bv[i - 512];
        ((float4*)g_bias)[i] = b;
    }
}

// ---------------- launch ---------------------------------------------------
extern "C" void kernel_launch(void* const* d_in, const int* in_sizes, int n_in,
                              void* d_out, int out_size) {
    const float* x  = (const float*)d_in[0];
    const float* Wq = (const float*)d_in[1];
    const float* bq = (const float*)d_in[2];
    const float* Wk = (const float*)d_in[3];
    const float* bk = (const float*)d_in[4];
    const float* Wv = (const float*)d_in[5];
    const float* bv = (const float*)d_in[6];
    const float* Wo = (const float*)d_in[7];
    const float* bo = (const float*)d_in[8];

    __half *pXh, *pWh, *pOh, *pQKV;
    float *pBias;
    cudaGetSymbolAddress((void**)&pXh,  g_Xh);
    cudaGetSymbolAddress((void**)&pWh,  g_Wh);
    cudaGetSymbolAddress((void**)&pOh,  g_Oh);
    cudaGetSymbolAddress((void**)&pQKV, g_QKVh);
    cudaGetSymbolAddress((void**)&pBias, g_bias);

    cudaFuncSetAttribute(gemm_h<__half>,
                         cudaFuncAttributeMaxDynamicSharedMemorySize, GH_SMEM);
    cudaFuncSetAttribute(gemm_h<float>,
                         cudaFuncAttributeMaxDynamicSharedMemorySize, GH_SMEM);
    cudaFuncSetAttribute(attn_mma,
                         cudaFuncAttributeMaxDynamicSharedMemorySize, ATT_SMEM);

    conv_fused<<<20480, 256>>>((const float4*)x,
                               (const float4*)Wq, (const float4*)Wk,
                               (const float4*)Wv, (const float4*)Wo,
                               (const float4*)bq, (const float4*)bk,
                               (const float4*)bv);

    // merged QKV GEMM: C[16384,3072] fp16
    gemm_h<__half><<<dim3(24, 128), 256, GH_SMEM>>>(pXh, pWh, pBias, pQKV, 3072);
    attn_mma<<<2048, 256, ATT_SMEM>>>();
    // final GEMM: fp32 out
    gemm_h<float><<<dim3(8, 128), 256, GH_SMEM>>>(pOh, pWh + 3145728, bo,
                                                  (float*)d_out, 1024);
}

// round 15
// speedup vs baseline: 1.4371x; 1.1124x over previous
#include <cuda_runtime.h>
#include <cuda_fp16.h>
#include <cstdint>
#include <math.h>

// N=4, S=4096, E=1024, H=16, D=64
// fused convert(x,W,bias) -> fp16 | ONE merged QKV GEMM [16384,3072] fp16-out
// | tensor-core head-gram attention (warp/position) | final GEMM fp32-out.
// R15 GEMM: CTA 128x128 with FOUR warps (warp tile 64x64, 2Mx2N), 2 CTAs/SM.
// Rationale: smem crossbar is the binder (ldmatrix bytes/mma); 64x64 warp
// tile cuts reads 192->128 B/mma, and 2 small CTAs per SM give two
// independent barrier domains (fixes R13's single-domain bubbles).

// ---------------- scratch (alloc-guard compliant device globals) ----------
__device__ __half g_Xh[16777216];      // x in fp16
__device__ __half g_QKVh[50331648];    // QKV merged output [16384,3072] fp16
__device__ __half g_Oh[16777216];      // attn out, scrambled, fp16
__device__ __half g_Wh[4194304];       // Wq,Wk,Wv,Wo in fp16 (concat)
__device__ float  g_bias[3072];        // bq|bk|bv concat

__device__ __forceinline__ uint32_t smem_u32(const void* p) {
    uint32_t a;
    asm("{ .reg .u64 t; cvta.to.shared.u64 t, %1; cvt.u32.u64 %0, t; }"
        : "=r"(a) : "l"(p));
    return a;
}

#define LDMX4(r0, r1, r2, r3, addr) \
    asm volatile("ldmatrix.sync.aligned.m8n8.x4.shared.b16 {%0,%1,%2,%3}, [%4];" \
                 : "=r"(r0), "=r"(r1), "=r"(r2), "=r"(r3) : "r"(addr))
#define LDMX4T(r0, r1, r2, r3, addr) \
    asm volatile("ldmatrix.sync.aligned.m8n8.x4.trans.shared.b16 {%0,%1,%2,%3}, [%4];" \
                 : "=r"(r0), "=r"(r1), "=r"(r2), "=r"(r3) : "r"(addr))
#define MMA16816(acc, a0, a1, a2, a3, b0, b1) \
    asm volatile("mma.sync.aligned.m16n8k16.row.col.f32.f16.f16.f32 " \
                 "{%0,%1,%2,%3}, {%4,%5,%6,%7}, {%8,%9}, {%0,%1,%2,%3};" \
                 : "+f"((acc)[0]), "+f"((acc)[1]), "+f"((acc)[2]), "+f"((acc)[3]) \
                 : "r"(a0), "r"(a1), "r"(a2), "r"(a3), "r"(b0), "r"(b1))

// ---------------------------------------------------------------------------
// fp16 GEMM: C[16384,NC] = Ah[16384,1024] @ Bh[NC,1024]^T + bias (fp32 acc)
// CTA tile 128x128, 128 threads (4 warps, 2Mx2N grid of 64x64 warp tiles),
// BK=32, 4-stage cp.async pipeline, mma.sync.m16n8k16 (4x8 atoms x 2 ksteps).
// smem row pitch 80B: 16B-aligned cp.async dsts AND conflict-free ldmatrix
// (banks (20r+c) mod 32 cover all 32 for rows r=0..7 of each phase).
// ---------------------------------------------------------------------------
static constexpr int GH_A_B     = 10240;           // 128 rows * 80B
static constexpr int GH_STAGE_B = 20480;           // (128 A + 128 B) * 80B
static constexpr int GH_SMEM    = 4 * GH_STAGE_B;  // 81920 per CTA (2 CTAs/SM)

template <typename OutT>
__global__ __launch_bounds__(128, 2)
void gemm_h(const __half* __restrict__ A, const __half* __restrict__ B,
            const float* __restrict__ bias, OutT* __restrict__ C, int ldc) {
    extern __shared__ __align__(128) char smem[];
    const uint32_t sb = smem_u32(smem);
    const int tid = threadIdx.x;
    const int warp = tid >> 5, lane = tid & 31;
    const int wm = (warp & 1) * 64;     // 2 warps along M
    const int wn = (warp >> 1) * 64;    // 2 warps along N

    const __half* Ab = A + (size_t)blockIdx.y * 128 * 1024;
    const __half* Bb = B + (size_t)blockIdx.x * 128 * 1024;

    float acc[4][8][4];
#pragma unroll
    for (int i = 0; i < 4; i++)
#pragma unroll
        for (int j = 0; j < 8; j++)
#pragma unroll
            for (int k = 0; k < 4; k++) acc[i][j][k] = 0.f;

    auto load_stage = [&](int v) {
        const uint32_t base = sb + (uint32_t)(v & 3) * GH_STAGE_B;
        const int kb = v * 32;
        // A: 128 rows x 32 halfs (4 x 16B chunks per row) = 512 chunks
#pragma unroll
        for (int i = 0; i < 4; i++) {
            const int c = tid + i * 128;       // 0..511
            const int row = c >> 2, ch = c & 3;
            const uint32_t da = base + (uint32_t)(row * 80 + ch * 16);
            asm volatile("cp.async.cg.shared.global [%0], [%1], 16;"
                         :: "r"(da), "l"(Ab + (size_t)row * 1024 + kb + ch * 8));
        }
        // B: 128 rows x 32 halfs
#pragma unroll
        for (int i = 0; i < 4; i++) {
            const int c = tid + i * 128;       // 0..511
            const int row = c >> 2, ch = c & 3;
            const uint32_t db = base + GH_A_B + (uint32_t)(row * 80 + ch * 16);
            asm volatile("cp.async.cg.shared.global [%0], [%1], 16;"
                         :: "r"(db), "l"(Bb + (size_t)row * 1024 + kb + ch * 8));
        }
    };

    load_stage(0); asm volatile("cp.async.commit_group;");
    load_stage(1); asm volatile("cp.async.commit_group;");
    load_stage(2); asm volatile("cp.async.commit_group;");

    // ldmatrix per-lane address components
    const int arow80 = (lane & 15) * 80;            // A rows m0..m0+15
    const int asel   = (lane >> 4) * 16;            // A: k or k+8 (bytes)
    const int brow80 = ((lane & 7) + ((lane >> 4) & 1) * 8) * 80;  // B rows n
    const int bsel   = ((lane >> 3) & 1) * 16;      // B: k or k+8 (bytes)

    for (int kt = 0; kt < 32; kt++) {
        asm volatile("cp.async.wait_group 2;");
        __syncthreads();                  // stage kt resident for all threads
        if (kt + 3 < 32) load_stage(kt + 3);
        asm volatile("cp.async.commit_group;");

        const uint32_t Abase = sb + (uint32_t)(kt & 3) * GH_STAGE_B;
        const uint32_t Bbase = Abase + GH_A_B;
#pragma unroll
        for (int ks = 0; ks < 2; ks++) {
            const int k0b = ks * 32;      // 16 halfs = 32 bytes
            uint32_t a[4][4];
#pragma unroll
            for (int am = 0; am < 4; am++) {
                const uint32_t ad = Abase +
                    (uint32_t)((wm + am * 16) * 80 + arow80 + k0b + asel);
                LDMX4(a[am][0], a[am][1], a[am][2], a[am][3], ad);
            }
            uint32_t b[8][2];
#pragma unroll
            for (int g = 0; g < 4; g++) {
                const uint32_t bd = Bbase +
                    (uint32_t)((wn + g * 16) * 80 + brow80 + k0b + bsel);
                uint32_t r0, r1, r2, r3;
                LDMX4(r0, r1, r2, r3, bd);
                b[2 * g][0] = r0; b[2 * g][1] = r1;
                b[2 * g + 1][0] = r2; b[2 * g + 1][1] = r3;
            }
#pragma unroll
            for (int am = 0; am < 4; am++)
#pragma unroll
                for (int bn = 0; bn < 8; bn++)
                    MMA16816(acc[am][bn], a[am][0], a[am][1], a[am][2], a[am][3],
                             b[bn][0], b[bn][1]);
        }
    }

    // epilogue: bias add + stores (fp32 or fp16 out)
    const int rowBase = blockIdx.y * 128 + wm + (lane >> 2);
    const int colBase = blockIdx.x * 128 + wn;
#pragma unroll
    for (int bn = 0; bn < 8; bn++) {
        const int col = colBase + bn * 8 + (lane & 3) * 2;
        const float b0 = bias[col];
        const float b1 = bias[col + 1];
#pragma unroll
        for (int am = 0; am < 4; am++) {
            const int row = rowBase + am * 16;
            if constexpr (sizeof(OutT) == 4) {
                float2 v;
                v.x = acc[am][bn][0] + b0;
                v.y = acc[am][bn][1] + b1;
                *(float2*)&C[(size_t)row * ldc + col] = v;
                v.x = acc[am][bn][2] + b0;
                v.y = acc[am][bn][3] + b1;
                *(float2*)&C[(size_t)(row + 8) * ldc + col] = v;
            } else {
                __half2 h;
                h = __floats2half2_rn(acc[am][bn][0] + b0, acc[am][bn][1] + b1);
                *(__half2*)&C[(size_t)row * ldc + col] = h;
                h = __floats2half2_rn(acc[am][bn][2] + b0, acc[am][bn][3] + b1);
                *(__half2*)&C[(size_t)(row + 8) * ldc + col] = h;
            }
        }
    }
}

// ---------------------------------------------------------------------------
// Tensor-core head-gram attention: ONE WARP PER POSITION (unchanged from R14,
// measured ~25us). QKV staged to warp-private smem (pitch 144B, conflict-free
// ldmatrix); gram via 8 HMMA; softmax on C frags via quad shuffles; P packed
// directly C->A fragment; out = P@V via ldmatrix.x4.trans + 8 HMMA. Store
// folds the reference's scrambled flat reshape: row' = q*256 + s/16,
// col' = (s%16)*64 + d. No __syncthreads anywhere.
// ---------------------------------------------------------------------------
static constexpr int ATT_WB   = 48 * 144;           // 6912 B per warp
static constexpr int ATT_SMEM = 8 * ATT_WB;         // 55296 B per block

__global__ __launch_bounds__(256)
void attn_mma() {
    extern __shared__ __align__(128) char asmem[];
    const int warpId = threadIdx.x >> 5;
    const int lane = threadIdx.x & 31;
    const int pos = blockIdx.x * 8 + warpId;
    const int s = pos & 4095;
    const int n = pos >> 12;

    const uint32_t wb = smem_u32(asmem) + (uint32_t)warpId * ATT_WB;
    const __half* src = g_QKVh + (size_t)pos * 3072;

    // stage 48 rows (Q:0-15, K:16-31, V:32-47), 64 halfs each, pitch 144B
#pragma unroll
    for (int it = 0; it < 12; it++) {
        const int id = it * 32 + lane;          // 0..383
        const int rr = id >> 3, cc = id & 7;
        const uint32_t dst = wb + (uint32_t)(rr * 144 + cc * 16);
        asm volatile("cp.async.cg.shared.global [%0], [%1], 16;"
                     :: "r"(dst), "l"(src + rr * 64 + cc * 8));
    }
    asm volatile("cp.async.commit_group;");
    asm volatile("cp.async.wait_group 0;");
    __syncwarp();

    const uint32_t Qb = wb;
    const uint32_t Kb = wb + 16 * 144;
    const uint32_t Vb = wb + 32 * 144;

    // ---- gram: C[2][4] covers 16x16 scores (2 n-octs) ----
    float c0[4] = {0.f, 0.f, 0.f, 0.f};
    float c1[4] = {0.f, 0.f, 0.f, 0.f};
    const uint32_t aAddr = Qb + (uint32_t)((lane & 15) * 144 + (lane >> 4) * 16);
    const uint32_t bAddr = Kb + (uint32_t)(((lane & 7) + ((lane >> 4) << 3)) * 144
                                           + ((lane >> 3) & 1) * 16);
#pragma unroll
    for (int kk = 0; kk < 4; kk++) {
        uint32_t a0, a1, a2, a3, m0, m1, m2, m3;
        LDMX4(a0, a1, a2, a3, aAddr + kk * 32);
        LDMX4(m0, m1, m2, m3, bAddr + kk * 32);
        MMA16816(c0, a0, a1, a2, a3, m0, m1);
        MMA16816(c1, a0, a1, a2, a3, m2, m3);
    }

    // ---- softmax on fragments (rows r = lane>>2 and r+8) ----
    float r0v[4] = {c0[0] * 0.125f, c0[1] * 0.125f, c1[0] * 0.125f, c1[1] * 0.125f};
    float r1v[4] = {c0[2] * 0.125f, c0[3] * 0.125f, c1[2] * 0.125f, c1[3] * 0.125f};
    float mx0 = fmaxf(fmaxf(r0v[0], r0v[1]), fmaxf(r0v[2], r0v[3]));
    float mx1 = fmaxf(fmaxf(r1v[0], r1v[1]), fmaxf(r1v[2], r1v[3]));
    mx0 = fmaxf(mx0, __shfl_xor_sync(0xffffffffu, mx0, 1));
    mx0 = fmaxf(mx0, __shfl_xor_sync(0xffffffffu, mx0, 2));
    mx1 = fmaxf(mx1, __shfl_xor_sync(0xffffffffu, mx1, 1));
    mx1 = fmaxf(mx1, __shfl_xor_sync(0xffffffffu, mx1, 2));
    float s0 = 0.f, s1 = 0.f;
#pragma unroll
    for (int i = 0; i < 4; i++) {
        r0v[i] = __expf(r0v[i] - mx0); s0 += r0v[i];
        r1v[i] = __expf(r1v[i] - mx1); s1 += r1v[i];
    }
    s0 += __shfl_xor_sync(0xffffffffu, s0, 1);
    s0 += __shfl_xor_sync(0xffffffffu, s0, 2);
    s1 += __shfl_xor_sync(0xffffffffu, s1, 1);
    s1 += __shfl_xor_sync(0xffffffffu, s1, 2);
    const float inv0 = 1.0f / s0, inv1 = 1.0f / s1;

    // ---- pack P to fp16 A-frags (direct C->A layout identity) ----
    __half2 pa0 = __floats2half2_rn(r0v[0] * inv0, r0v[1] * inv0);
    __half2 pa1 = __floats2half2_rn(r1v[0] * inv1, r1v[1] * inv1);
    __half2 pa2 = __floats2half2_rn(r0v[2] * inv0, r0v[3] * inv0);
    __half2 pa3 = __floats2half2_rn(r1v[2] * inv1, r1v[3] * inv1);
    const uint32_t p0 = *(uint32_t*)&pa0, p1 = *(uint32_t*)&pa1;
    const uint32_t p2 = *(uint32_t*)&pa2, p3 = *(uint32_t*)&pa3;

    // ---- out = P @ V : 8 n-chunks of 8 cols ----
    float o[8][4];
#pragma unroll
    for (int ch = 0; ch < 8; ch++)
#pragma unroll
        for (int k = 0; k < 4; k++) o[ch][k] = 0.f;
    const uint32_t vAddr = Vb + (uint32_t)((lane & 15) * 144 + (lane >> 4) * 16);
#pragma unroll
    for (int i = 0; i < 4; i++) {
        uint32_t m0, m1, m2, m3;
        LDMX4T(m0, m1, m2, m3, vAddr + i * 32);
        MMA16816(o[2 * i],     p0, p1, p2, p3, m0, m1);
        MMA16816(o[2 * i + 1], p0, p1, p2, p3, m2, m3);
    }

    // ---- scrambled store, fp16 ----
    const int r = lane >> 2, c2 = (lane & 3) * 2;
    const size_t base2 = (((size_t)n << 12) + (size_t)(s >> 4)) * 1024
                       + (size_t)(s & 15) * 64;
#pragma unroll
    for (int ch = 0; ch < 8; ch++) {
        const int d = ch * 8 + c2;
        __half2 lo = __floats2half2_rn(o[ch][0], o[ch][1]);
        __half2 hi = __floats2half2_rn(o[ch][2], o[ch][3]);
        *(__half2*)&g_Oh[base2 + (size_t)r * 262144 + d] = lo;
        *(__half2*)&g_Oh[base2 + (size_t)(r + 8) * 262144 + d] = hi;
    }
}

// ---------------- fused conversion: x + 4 weights + bias concat ------------
__global__ __launch_bounds__(256)
void conv_fused(const float4* __restrict__ x,
                const float4* __restrict__ wq, const float4* __restrict__ wk,
                const float4* __restrict__ wv, const float4* __restrict__ wo,
                const float4* __restrict__ bq, const float4* __restrict__ bk,
                const float4* __restrict__ bv) {
    const int i = blockIdx.x * 256 + threadIdx.x;
    float4 v;
    uint2* dst;
    if (i < 4194304) {
        v = x[i];
        dst = (uint2*)g_Xh + i;
    } else {
        const int w = i - 4194304;           // 0..1048575
        const int seg = w >> 18;             // 0..3
        const int off = w & 262143;
        v = (seg == 0) ? wq[off] : (seg == 1) ? wk[off]
          : (seg == 2) ? wv[off] : wo[off];
        dst = (uint2*)g_Wh + w;
    }
    __half2 h0 = __floats2half2_rn(v.x, v.y);
    __half2 h1 = __floats2half2_rn(v.z, v.w);
    uint2 o;
    o.x = *(uint32_t*)&h0;
    o.y = *(uint32_t*)&h1;
    *dst = o;

    if (i < 768) {  // bias concat (3072 floats = 768 float4)
        float4 b = (i < 256) ? bq[i] : (i < 512) ? bk[i - 256] : bv[i - 512];
        ((float4*)g_bias)[i] = b;
    }
}

// ---------------- launch ---------------------------------------------------
extern "C" void kernel_launch(void* const* d_in, const int* in_sizes, int n_in,
                              void* d_out, int out_size) {
    const float* x  = (const float*)d_in[0];
    const float* Wq = (const float*)d_in[1];
    const float* bq = (const float*)d_in[2];
    const float* Wk = (const float*)d_in[3];
    const float* bk = (const float*)d_in[4];
    const float* Wv = (const float*)d_in[5];
    const float* bv = (const float*)d_in[6];
    const float* Wo = (const float*)d_in[7];
    const float* bo = (const float*)d_in[8];

    __half *pXh, *pWh, *pOh, *pQKV;
    float *pBias;
    cudaGetSymbolAddress((void**)&pXh,  g_Xh);
    cudaGetSymbolAddress((void**)&pWh,  g_Wh);
    cudaGetSymbolAddress((void**)&pOh,  g_Oh);
    cudaGetSymbolAddress((void**)&pQKV, g_QKVh);
    cudaGetSymbolAddress((void**)&pBias, g_bias);

    cudaFuncSetAttribute(gemm_h<__half>,
                         cudaFuncAttributeMaxDynamicSharedMemorySize, GH_SMEM);
    cudaFuncSetAttribute(gemm_h<float>,
                         cudaFuncAttributeMaxDynamicSharedMemorySize, GH_SMEM);
    cudaFuncSetAttribute(attn_mma,
                         cudaFuncAttributeMaxDynamicSharedMemorySize, ATT_SMEM);

    conv_fused<<<20480, 256>>>((const float4*)x,
                               (const float4*)Wq, (const float4*)Wk,
                               (const float4*)Wv, (const float4*)Wo,
                               (const float4*)bq, (const float4*)bk,
                               (const float4*)bv);

    // merged QKV GEMM: C[16384,3072] fp16
    gemm_h<__half><<<dim3(24, 128), 128, GH_SMEM>>>(pXh, pWh, pBias, pQKV, 3072);
    attn_mma<<<2048, 256, ATT_SMEM>>>();
    // final GEMM: fp32 out
    gemm_h<float><<<dim3(8, 128), 128, GH_SMEM>>>(pOh, pWh + 3145728, bo,
                                                  (float*)d_out, 1024);
}